// round 1
// baseline (speedup 1.0000x reference)
#include <cuda_runtime.h>
#include <cstddef>

#define NN 20000
#define NE 200000
#define NG 128
#define HID 256
#define BHD 256

// ---------------- scratch (device globals; no allocations allowed) ---------
__device__ float g_n1[NN * BHD];
__device__ float g_e1[NE * BHD];
__device__ float g_g1[NG * BHD];
__device__ float g_ein[(size_t)NE * 4 * BHD];   // edge MLP input  [E,1024]
__device__ float g_emid[NE * BHD];              // e after edge MLP
__device__ float g_nin[NN * 3 * BHD];           // node MLP input  [N,768]
__device__ float g_nmid[NN * BHD];              // n after node MLP
__device__ float g_e2n[NN * BHD];               // scatter sums
__device__ float g_e2g[NG * BHD];
__device__ float g_n2g[NG * BHD];
__device__ float g_gin[NG * 3 * BHD];
__device__ float g_gmid[NG * BHD];
__device__ float g_ncnt[NN];
__device__ float g_gcnt_e[NG];
__device__ float g_gcnt_n[NG];

__device__ __forceinline__ float ssp(float x) {
    // softplus(x) - log(2), numerically stable
    return fmaxf(x, 0.0f) + log1pf(__expf(-fabsf(x))) - 0.69314718055994531f;
}

// ---------------- zero fill -------------------------------------------------
__global__ void zero_kernel(float* __restrict__ p, size_t n) {
    size_t i = (size_t)blockIdx.x * blockDim.x + threadIdx.x;
    if (i < n) p[i] = 0.0f;
}

// ---------------- SGEMM: C = ssp(A @ W^T) [+ R] -----------------------------
// A [M,K] row-major, W [N,K] row-major, C [M,N]. 128x128x8 tile, 8x8 microtile
// (split 4+4 halves for conflict-free LDS.128 reads). 256 threads.
#define BM 128
#define BN 128
#define BK 8

template <int ADD>
__global__ __launch_bounds__(256) void gemm_ssp_kernel(
    const float* __restrict__ A, const float* __restrict__ W,
    const float* __restrict__ R, float* __restrict__ C,
    int M, int N, int K)
{
    __shared__ float As[BK][BM];
    __shared__ float Ws[BK][BN];

    const int tid = threadIdx.x;
    const int m0 = blockIdx.y * BM;
    const int n0 = blockIdx.x * BN;
    const int ty = tid >> 4;        // 0..15
    const int tx = tid & 15;        // 0..15

    // loader mapping: each thread loads one float4 of A-tile and W-tile
    const int lrow = tid >> 1;            // 0..127
    const int lk   = (tid & 1) * 4;       // 0 or 4
    const bool arow_ok = (m0 + lrow) < M;
    const float* Aptr = A + (size_t)(m0 + lrow) * K + lk;
    const float* Wptr = W + (size_t)(n0 + lrow) * K + lk;

    float acc[2][4][2][4];
#pragma unroll
    for (int rh = 0; rh < 2; rh++)
#pragma unroll
        for (int i = 0; i < 4; i++)
#pragma unroll
            for (int ch = 0; ch < 2; ch++)
#pragma unroll
                for (int j = 0; j < 4; j++) acc[rh][i][ch][j] = 0.0f;

    for (int k0 = 0; k0 < K; k0 += BK) {
        float4 av = arow_ok ? *(const float4*)(Aptr + k0)
                            : make_float4(0.f, 0.f, 0.f, 0.f);
        float4 wv = *(const float4*)(Wptr + k0);
        __syncthreads();
        As[lk + 0][lrow] = av.x; As[lk + 1][lrow] = av.y;
        As[lk + 2][lrow] = av.z; As[lk + 3][lrow] = av.w;
        Ws[lk + 0][lrow] = wv.x; Ws[lk + 1][lrow] = wv.y;
        Ws[lk + 2][lrow] = wv.z; Ws[lk + 3][lrow] = wv.w;
        __syncthreads();

#pragma unroll
        for (int kk = 0; kk < BK; kk++) {
            float4 a0 = *(const float4*)&As[kk][ty * 4];
            float4 a1 = *(const float4*)&As[kk][64 + ty * 4];
            float4 b0 = *(const float4*)&Ws[kk][tx * 4];
            float4 b1 = *(const float4*)&Ws[kk][64 + tx * 4];
            float a[2][4] = {{a0.x, a0.y, a0.z, a0.w}, {a1.x, a1.y, a1.z, a1.w}};
            float b[2][4] = {{b0.x, b0.y, b0.z, b0.w}, {b1.x, b1.y, b1.z, b1.w}};
#pragma unroll
            for (int rh = 0; rh < 2; rh++)
#pragma unroll
                for (int i = 0; i < 4; i++)
#pragma unroll
                    for (int ch = 0; ch < 2; ch++)
#pragma unroll
                        for (int j = 0; j < 4; j++)
                            acc[rh][i][ch][j] += a[rh][i] * b[ch][j];
        }
    }

#pragma unroll
    for (int rh = 0; rh < 2; rh++) {
#pragma unroll
        for (int i = 0; i < 4; i++) {
            int r = m0 + rh * 64 + ty * 4 + i;
            if (r >= M) continue;
#pragma unroll
            for (int ch = 0; ch < 2; ch++) {
                int c = n0 + ch * 64 + tx * 4;
                float4 o;
                o.x = ssp(acc[rh][i][ch][0]);
                o.y = ssp(acc[rh][i][ch][1]);
                o.z = ssp(acc[rh][i][ch][2]);
                o.w = ssp(acc[rh][i][ch][3]);
                if (ADD) {
                    float4 rv = *(const float4*)&R[(size_t)r * N + c];
                    o.x += rv.x; o.y += rv.y; o.z += rv.z; o.w += rv.w;
                }
                *(float4*)&C[(size_t)r * N + c] = o;
            }
        }
    }
}

// ---------------- gather: edge_in = [n1[src], n1[dst], e1, g1[batch[src]]] --
__global__ __launch_bounds__(256) void build_edge_in_kernel(
    const int* __restrict__ src, const int* __restrict__ dst,
    const int* __restrict__ batch)
{
    int e = blockIdx.x;
    int t = threadIdx.x;                 // float4 index within 1024 floats
    int s = src[e];
    int d = dst[e];
    int b = batch[s];
    const float4* n1 = (const float4*)g_n1;
    const float4* e1 = (const float4*)g_e1;
    const float4* g1 = (const float4*)g_g1;
    int seg = t >> 6, w = t & 63;
    float4 v;
    if (seg == 0)      v = n1[(size_t)s * 64 + w];
    else if (seg == 1) v = n1[(size_t)d * 64 + w];
    else if (seg == 2) v = e1[(size_t)e * 64 + w];
    else               v = g1[(size_t)b * 64 + w];
    ((float4*)g_ein)[(size_t)e * 256 + t] = v;
}

// ---------------- scatter e_mid -> nodes (by dst) and graphs (by batch[src])
__global__ __launch_bounds__(256) void scatter_edges_kernel(
    const int* __restrict__ src, const int* __restrict__ dst,
    const int* __restrict__ batch)
{
    int e = blockIdx.x;
    int c = threadIdx.x;
    float v = g_emid[(size_t)e * BHD + c];
    int d = dst[e];
    atomicAdd(&g_e2n[(size_t)d * BHD + c], v);
    int b = batch[src[e]];
    atomicAdd(&g_e2g[(size_t)b * BHD + c], v);
    if (c == 0) {
        atomicAdd(&g_ncnt[d], 1.0f);
        atomicAdd(&g_gcnt_e[b], 1.0f);
    }
}

// ---------------- scatter n_mid -> graphs (by batch) ------------------------
__global__ __launch_bounds__(256) void scatter_nodes_kernel(
    const int* __restrict__ batch)
{
    int v = blockIdx.x;
    int c = threadIdx.x;
    int b = batch[v];
    atomicAdd(&g_n2g[(size_t)b * BHD + c], g_nmid[(size_t)v * BHD + c]);
    if (c == 0) atomicAdd(&g_gcnt_n[b], 1.0f);
}

// ---------------- node_in = [n1, e2n_mean, g1[batch]] -----------------------
__global__ __launch_bounds__(192) void build_node_in_kernel(
    const int* __restrict__ batch)
{
    int v = blockIdx.x;
    int t = threadIdx.x;                 // 0..191 float4 slots of 768 floats
    int seg = t / 64, w = t % 64;
    float4 val;
    if (seg == 0) {
        val = ((const float4*)g_n1)[(size_t)v * 64 + w];
    } else if (seg == 1) {
        float cnt = fmaxf(g_ncnt[v], 1.0f);
        float inv = 1.0f / cnt;
        float4 s = ((const float4*)g_e2n)[(size_t)v * 64 + w];
        val = make_float4(s.x * inv, s.y * inv, s.z * inv, s.w * inv);
    } else {
        int b = batch[v];
        val = ((const float4*)g_g1)[(size_t)b * 64 + w];
    }
    ((float4*)g_nin)[(size_t)v * 192 + t] = val;
}

// ---------------- glob_in = [n2g_mean, e2g_mean, g1] ------------------------
__global__ __launch_bounds__(192) void build_glob_in_kernel()
{
    int gidx = blockIdx.x;
    int t = threadIdx.x;
    int seg = t / 64, w = t % 64;
    float4 val;
    if (seg == 0) {
        float inv = 1.0f / fmaxf(g_gcnt_n[gidx], 1.0f);
        float4 s = ((const float4*)g_n2g)[(size_t)gidx * 64 + w];
        val = make_float4(s.x * inv, s.y * inv, s.z * inv, s.w * inv);
    } else if (seg == 1) {
        float inv = 1.0f / fmaxf(g_gcnt_e[gidx], 1.0f);
        float4 s = ((const float4*)g_e2g)[(size_t)gidx * 64 + w];
        val = make_float4(s.x * inv, s.y * inv, s.z * inv, s.w * inv);
    } else {
        val = ((const float4*)g_g1)[(size_t)gidx * 64 + w];
    }
    ((float4*)g_gin)[(size_t)gidx * 192 + t] = val;
}

// ---------------- host side --------------------------------------------------
static inline void zero_buf(float* p, size_t n) {
    zero_kernel<<<(unsigned)((n + 255) / 256), 256>>>(p, n);
}

static inline void gemm(const float* A, const float* W, float* C,
                        int M, int N, int K) {
    dim3 grid(N / BN, (M + BM - 1) / BM);
    gemm_ssp_kernel<0><<<grid, 256>>>(A, W, nullptr, C, M, N, K);
}
static inline void gemm_add(const float* A, const float* W, const float* R,
                            float* C, int M, int N, int K) {
    dim3 grid(N / BN, (M + BM - 1) / BM);
    gemm_ssp_kernel<1><<<grid, 256>>>(A, W, R, C, M, N, K);
}

template <typename T>
static T* sym(const void* symbol) {
    void* p = nullptr;
    cudaGetSymbolAddress(&p, symbol);
    return (T*)p;
}

extern "C" void kernel_launch(void* const* d_in, const int* in_sizes, int n_in,
                              void* d_out, int out_size) {
    const float* node_feats = (const float*)d_in[0];
    const float* edge_feats = (const float*)d_in[1];
    const float* glob_feats = (const float*)d_in[2];
    const int*   edge_index = (const int*)d_in[3];
    const int*   batch      = (const int*)d_in[4];
    const float* W_node1    = (const float*)d_in[5];
    const float* W_edge1    = (const float*)d_in[6];
    const float* W_glob1    = (const float*)d_in[7];
    const float* W_edge_mlp = (const float*)d_in[8];
    const float* W_node_mlp = (const float*)d_in[9];
    const float* W_glob_mlp = (const float*)d_in[10];
    const float* W_node2    = (const float*)d_in[11];
    const float* W_edge2    = (const float*)d_in[12];
    const float* W_glob2    = (const float*)d_in[13];

    const int* src = edge_index;         // edge_index[0]
    const int* dst = edge_index + NE;    // edge_index[1]

    float* out = (float*)d_out;
    float* out_n = out;                          // [NN, 256]
    float* out_e = out + (size_t)NN * BHD;       // [NE, 256]
    float* out_g = out + (size_t)(NN + NE) * BHD;// [NG, 256]

    float* p_n1   = sym<float>(g_n1);
    float* p_e1   = sym<float>(g_e1);
    float* p_g1   = sym<float>(g_g1);
    float* p_ein  = sym<float>(g_ein);
    float* p_emid = sym<float>(g_emid);
    float* p_nin  = sym<float>(g_nin);
    float* p_nmid = sym<float>(g_nmid);
    float* p_e2n  = sym<float>(g_e2n);
    float* p_e2g  = sym<float>(g_e2g);
    float* p_n2g  = sym<float>(g_n2g);
    float* p_gin  = sym<float>(g_gin);
    float* p_gmid = sym<float>(g_gmid);
    float* p_ncnt  = sym<float>(g_ncnt);
    float* p_gcnte = sym<float>(g_gcnt_e);
    float* p_gcntn = sym<float>(g_gcnt_n);

    // zero scatter accumulators (graph replays need this every call)
    zero_buf(p_e2n, (size_t)NN * BHD);
    zero_buf(p_e2g, (size_t)NG * BHD);
    zero_buf(p_n2g, (size_t)NG * BHD);
    zero_buf(p_ncnt, NN);
    zero_buf(p_gcnte, NG);
    zero_buf(p_gcntn, NG);

    // stage 1: input projections + ssp
    gemm(node_feats, W_node1, p_n1, NN, BHD, HID);
    gemm(edge_feats, W_edge1, p_e1, NE, BHD, HID);
    gemm(glob_feats, W_glob1, p_g1, NG, BHD, HID);

    // EdgeModel
    build_edge_in_kernel<<<NE, 256>>>(src, dst, batch);
    gemm(p_ein, W_edge_mlp, p_emid, NE, BHD, 4 * BHD);

    // scatter e -> nodes and graphs
    scatter_edges_kernel<<<NE, 256>>>(src, dst, batch);

    // NodeModel
    build_node_in_kernel<<<NN, 192>>>(batch);
    gemm(p_nin, W_node_mlp, p_nmid, NN, BHD, 3 * BHD);

    // scatter n -> graphs
    scatter_nodes_kernel<<<NN, 256>>>(batch);

    // GlobalModel
    build_glob_in_kernel<<<NG, 192>>>();
    gemm(p_gin, W_glob_mlp, p_gmid, NG, BHD, 3 * BHD);

    // output projections + ssp + residual
    gemm_add(p_nmid, W_node2, node_feats, out_n, NN, BHD, BHD);
    gemm_add(p_emid, W_edge2, edge_feats, out_e, NE, BHD, BHD);
    gemm_add(p_gmid, W_glob2, glob_feats, out_g, NG, BHD, BHD);
}

// round 2
// speedup vs baseline: 2.1824x; 2.1824x over previous
#include <cuda_runtime.h>
#include <cstddef>
#include <cstdint>

#define NN 20000
#define NE 200000
#define NG 128
#define HID 256
#define BHD 256

// ---------------- scratch (device globals; no allocations allowed) ---------
__device__ float g_n1[NN * BHD];
__device__ float g_e1[NE * BHD];
__device__ float g_g1[NG * BHD];
__device__ float g_emid[NE * BHD];              // e after edge MLP
__device__ float g_nin[NN * 3 * BHD];           // node MLP input  [N,768]
__device__ float g_nmid[NN * BHD];              // n after node MLP
__device__ float g_e2n[NN * BHD];               // scatter sums
__device__ float g_e2g[NG * BHD];
__device__ float g_n2g[NG * BHD];
__device__ float g_gin[NG * 3 * BHD];
__device__ float g_gmid[NG * BHD];
__device__ float g_ncnt[NN];
__device__ float g_gcnt_e[NG];
__device__ float g_gcnt_n[NG];

__device__ __forceinline__ float ssp(float x) {
    return fmaxf(x, 0.0f) + log1pf(__expf(-fabsf(x))) - 0.69314718055994531f;
}

// ---------------- zero fill -------------------------------------------------
__global__ void zero_kernel(float* __restrict__ p, size_t n) {
    size_t i = (size_t)blockIdx.x * blockDim.x + threadIdx.x;
    if (i < n) p[i] = 0.0f;
}

// ---------------- TF32 tensor-core GEMM ------------------------------------
// C[M,256] = ssp(A[M,K] @ W[256,K]^T) (+R). Block tile 128x128x16, 8 warps of
// 32x64, 2-stage cp.async pipeline. MODE 1 fuses the edge gather: logical
// A row e = [n1[src[e]], n1[dst[e]], e1[e], g1[batch[src[e]]]] (K=1024).
#define TBM 128
#define TBN 128
#define TBK 16
#define SST 20          // padded smem row stride (floats): conflict-free frags
#define SBUF (TBM * SST)// floats per buffer

__device__ __forceinline__ uint32_t f2tf32(float f) {
    uint32_t r;
    asm("cvt.rna.tf32.f32 %0, %1;" : "=r"(r) : "f"(f));
    return r;
}

__device__ __forceinline__ void mma_tf32(float* c,
    uint32_t a0, uint32_t a1, uint32_t a2, uint32_t a3,
    uint32_t b0, uint32_t b1)
{
    asm volatile(
        "mma.sync.aligned.m16n8k8.row.col.f32.tf32.tf32.f32 "
        "{%0,%1,%2,%3},{%4,%5,%6,%7},{%8,%9},{%0,%1,%2,%3};\n"
        : "+f"(c[0]), "+f"(c[1]), "+f"(c[2]), "+f"(c[3])
        : "r"(a0), "r"(a1), "r"(a2), "r"(a3), "r"(b0), "r"(b1));
}

__device__ __forceinline__ void cp16(uint32_t saddr, const void* g) {
    asm volatile("cp.async.cg.shared.global [%0], [%1], 16;\n"
                 :: "r"(saddr), "l"(g));
}

template <int MODE, int ADD>
__global__ __launch_bounds__(256) void mma_gemm(
    const float* __restrict__ A, const float* __restrict__ W,
    const float* __restrict__ R, float* __restrict__ C,
    int M, int K,
    const int* __restrict__ src, const int* __restrict__ dst,
    const int* __restrict__ batch)
{
    __shared__ float As[2][TBM][SST];
    __shared__ float Ws[2][TBN][SST];

    const int tid = threadIdx.x;
    const int m0 = blockIdx.y * TBM;
    const int n0 = blockIdx.x * TBN;

    // ---- loaders: thread -> (row, col-half) of the 128x16 tile
    const int lrow = tid >> 1;
    const int lc0 = (tid & 1) * 8;

    const float* aptr = nullptr;
    const float* ps = nullptr; const float* pd = nullptr;
    const float* pe = nullptr; const float* pg = nullptr;
    if (MODE == 0) {
        int r = min(m0 + lrow, M - 1);
        aptr = A + (size_t)r * K;
    } else {
        int e = min(m0 + lrow, NE - 1);
        int s = src[e], d = dst[e], b = batch[s];
        ps = g_n1 + (size_t)s * 256;
        pd = g_n1 + (size_t)d * 256;
        pe = g_e1 + (size_t)e * 256;
        pg = g_g1 + (size_t)b * 256;
    }
    const float* wptr = W + (size_t)(n0 + lrow) * K;

    uint32_t sA = (uint32_t)__cvta_generic_to_shared(&As[0][0][0]);
    uint32_t sW = (uint32_t)__cvta_generic_to_shared(&Ws[0][0][0]);
    const uint32_t loff = (uint32_t)(lrow * SST + lc0) * 4u;

    auto load_tile = [&](int kt, int buf) {
        int k0 = kt * TBK;
        const float* ap;
        if (MODE == 0) {
            ap = aptr + k0;
        } else {
            int seg = k0 >> 8;
            int ko = k0 & 255;
            const float* base = (seg == 0) ? ps : (seg == 1) ? pd
                              : (seg == 2) ? pe : pg;
            ap = base + ko;
        }
        uint32_t da = sA + (uint32_t)buf * (SBUF * 4) + loff;
        uint32_t dw = sW + (uint32_t)buf * (SBUF * 4) + loff;
        cp16(da,      ap + lc0);
        cp16(da + 16, ap + lc0 + 4);
        const float* wp = wptr + k0;
        cp16(dw,      wp + lc0);
        cp16(dw + 16, wp + lc0 + 4);
        asm volatile("cp.async.commit_group;\n" ::: "memory");
    };

    // ---- compute mapping
    const int lane = tid & 31, warp = tid >> 5;
    const int wm = (warp & 3) * 32;   // warp m offset in block
    const int wn = (warp >> 2) * 64;  // warp n offset in block
    const int gid = lane >> 2, tig = lane & 3;

    float acc[2][8][4];
#pragma unroll
    for (int mt = 0; mt < 2; mt++)
#pragma unroll
        for (int nt = 0; nt < 8; nt++)
#pragma unroll
            for (int i = 0; i < 4; i++) acc[mt][nt][i] = 0.0f;

    const int KT = K / TBK;
    load_tile(0, 0);

    for (int kt = 0; kt < KT; kt++) {
        asm volatile("cp.async.wait_group 0;\n" ::: "memory");
        __syncthreads();
        if (kt + 1 < KT) load_tile(kt + 1, (kt + 1) & 1);
        const int buf = kt & 1;

#pragma unroll
        for (int ks = 0; ks < 2; ks++) {
            const int k = ks * 8;
            uint32_t B0[8], B1[8];
#pragma unroll
            for (int nt = 0; nt < 8; nt++) {
                int r = wn + nt * 8 + gid;
                B0[nt] = f2tf32(Ws[buf][r][k + tig]);
                B1[nt] = f2tf32(Ws[buf][r][k + tig + 4]);
            }
#pragma unroll
            for (int mt = 0; mt < 2; mt++) {
                int r = wm + mt * 16 + gid;
                uint32_t a0 = f2tf32(As[buf][r][k + tig]);
                uint32_t a1 = f2tf32(As[buf][r + 8][k + tig]);
                uint32_t a2 = f2tf32(As[buf][r][k + tig + 4]);
                uint32_t a3 = f2tf32(As[buf][r + 8][k + tig + 4]);
#pragma unroll
                for (int nt = 0; nt < 8; nt++)
                    mma_tf32(acc[mt][nt], a0, a1, a2, a3, B0[nt], B1[nt]);
            }
        }
        __syncthreads();
    }

    // ---- epilogue: ssp (+residual), N fixed at 256
#pragma unroll
    for (int mt = 0; mt < 2; mt++) {
#pragma unroll
        for (int nt = 0; nt < 8; nt++) {
            const float* a = acc[mt][nt];
            int r0 = m0 + wm + mt * 16 + gid;
            int cc = n0 + wn + nt * 8 + tig * 2;
            if (r0 < M) {
                float2 o = make_float2(ssp(a[0]), ssp(a[1]));
                if (ADD) {
                    float2 rv = *(const float2*)&R[(size_t)r0 * 256 + cc];
                    o.x += rv.x; o.y += rv.y;
                }
                *(float2*)&C[(size_t)r0 * 256 + cc] = o;
            }
            int r1 = r0 + 8;
            if (r1 < M) {
                float2 o = make_float2(ssp(a[2]), ssp(a[3]));
                if (ADD) {
                    float2 rv = *(const float2*)&R[(size_t)r1 * 256 + cc];
                    o.x += rv.x; o.y += rv.y;
                }
                *(float2*)&C[(size_t)r1 * 256 + cc] = o;
            }
        }
    }
}

// ---------------- scatter e_mid -> nodes (by dst) and graphs (by batch[src])
__global__ __launch_bounds__(256) void scatter_edges_kernel(
    const int* __restrict__ src, const int* __restrict__ dst,
    const int* __restrict__ batch)
{
    int e = blockIdx.x;
    int c = threadIdx.x;
    float v = g_emid[(size_t)e * BHD + c];
    int d = dst[e];
    atomicAdd(&g_e2n[(size_t)d * BHD + c], v);
    int b = batch[src[e]];
    atomicAdd(&g_e2g[(size_t)b * BHD + c], v);
    if (c == 0) {
        atomicAdd(&g_ncnt[d], 1.0f);
        atomicAdd(&g_gcnt_e[b], 1.0f);
    }
}

// ---------------- scatter n_mid -> graphs (by batch) ------------------------
__global__ __launch_bounds__(256) void scatter_nodes_kernel(
    const int* __restrict__ batch)
{
    int v = blockIdx.x;
    int c = threadIdx.x;
    int b = batch[v];
    atomicAdd(&g_n2g[(size_t)b * BHD + c], g_nmid[(size_t)v * BHD + c]);
    if (c == 0) atomicAdd(&g_gcnt_n[b], 1.0f);
}

// ---------------- node_in = [n1, e2n_mean, g1[batch]] -----------------------
__global__ __launch_bounds__(192) void build_node_in_kernel(
    const int* __restrict__ batch)
{
    int v = blockIdx.x;
    int t = threadIdx.x;
    int seg = t / 64, w = t % 64;
    float4 val;
    if (seg == 0) {
        val = ((const float4*)g_n1)[(size_t)v * 64 + w];
    } else if (seg == 1) {
        float inv = 1.0f / fmaxf(g_ncnt[v], 1.0f);
        float4 s = ((const float4*)g_e2n)[(size_t)v * 64 + w];
        val = make_float4(s.x * inv, s.y * inv, s.z * inv, s.w * inv);
    } else {
        int b = batch[v];
        val = ((const float4*)g_g1)[(size_t)b * 64 + w];
    }
    ((float4*)g_nin)[(size_t)v * 192 + t] = val;
}

// ---------------- glob_in = [n2g_mean, e2g_mean, g1] ------------------------
__global__ __launch_bounds__(192) void build_glob_in_kernel()
{
    int gidx = blockIdx.x;
    int t = threadIdx.x;
    int seg = t / 64, w = t % 64;
    float4 val;
    if (seg == 0) {
        float inv = 1.0f / fmaxf(g_gcnt_n[gidx], 1.0f);
        float4 s = ((const float4*)g_n2g)[(size_t)gidx * 64 + w];
        val = make_float4(s.x * inv, s.y * inv, s.z * inv, s.w * inv);
    } else if (seg == 1) {
        float inv = 1.0f / fmaxf(g_gcnt_e[gidx], 1.0f);
        float4 s = ((const float4*)g_e2g)[(size_t)gidx * 64 + w];
        val = make_float4(s.x * inv, s.y * inv, s.z * inv, s.w * inv);
    } else {
        val = ((const float4*)g_g1)[(size_t)gidx * 64 + w];
    }
    ((float4*)g_gin)[(size_t)gidx * 192 + t] = val;
}

// ---------------- host side --------------------------------------------------
static inline void zero_buf(float* p, size_t n) {
    zero_kernel<<<(unsigned)((n + 255) / 256), 256>>>(p, n);
}

static inline void gemm(const float* A, const float* W, float* C, int M, int K) {
    dim3 grid(2, (M + TBM - 1) / TBM);
    mma_gemm<0, 0><<<grid, 256>>>(A, W, nullptr, C, M, K,
                                  nullptr, nullptr, nullptr);
}
static inline void gemm_add(const float* A, const float* W, const float* R,
                            float* C, int M, int K) {
    dim3 grid(2, (M + TBM - 1) / TBM);
    mma_gemm<0, 1><<<grid, 256>>>(A, W, R, C, M, K,
                                  nullptr, nullptr, nullptr);
}
static inline void gemm_edge(const float* W, float* C,
                             const int* src, const int* dst, const int* batch) {
    dim3 grid(2, (NE + TBM - 1) / TBM);
    mma_gemm<1, 0><<<grid, 256>>>(nullptr, W, nullptr, C, NE, 4 * BHD,
                                  src, dst, batch);
}

template <typename T>
static T* sym(const void* symbol) {
    void* p = nullptr;
    cudaGetSymbolAddress(&p, symbol);
    return (T*)p;
}

extern "C" void kernel_launch(void* const* d_in, const int* in_sizes, int n_in,
                              void* d_out, int out_size) {
    const float* node_feats = (const float*)d_in[0];
    const float* edge_feats = (const float*)d_in[1];
    const float* glob_feats = (const float*)d_in[2];
    const int*   edge_index = (const int*)d_in[3];
    const int*   batch      = (const int*)d_in[4];
    const float* W_node1    = (const float*)d_in[5];
    const float* W_edge1    = (const float*)d_in[6];
    const float* W_glob1    = (const float*)d_in[7];
    const float* W_edge_mlp = (const float*)d_in[8];
    const float* W_node_mlp = (const float*)d_in[9];
    const float* W_glob_mlp = (const float*)d_in[10];
    const float* W_node2    = (const float*)d_in[11];
    const float* W_edge2    = (const float*)d_in[12];
    const float* W_glob2    = (const float*)d_in[13];

    const int* src = edge_index;
    const int* dst = edge_index + NE;

    float* out = (float*)d_out;
    float* out_n = out;
    float* out_e = out + (size_t)NN * BHD;
    float* out_g = out + (size_t)(NN + NE) * BHD;

    float* p_n1   = sym<float>(g_n1);
    float* p_e1   = sym<float>(g_e1);
    float* p_g1   = sym<float>(g_g1);
    float* p_emid = sym<float>(g_emid);
    float* p_nin  = sym<float>(g_nin);
    float* p_nmid = sym<float>(g_nmid);
    float* p_e2n  = sym<float>(g_e2n);
    float* p_e2g  = sym<float>(g_e2g);
    float* p_n2g  = sym<float>(g_n2g);
    float* p_gin  = sym<float>(g_gin);
    float* p_gmid = sym<float>(g_gmid);
    float* p_ncnt  = sym<float>(g_ncnt);
    float* p_gcnte = sym<float>(g_gcnt_e);
    float* p_gcntn = sym<float>(g_gcnt_n);

    // zero scatter accumulators (graph replays need this every call)
    zero_buf(p_e2n, (size_t)NN * BHD);
    zero_buf(p_e2g, (size_t)NG * BHD);
    zero_buf(p_n2g, (size_t)NG * BHD);
    zero_buf(p_ncnt, NN);
    zero_buf(p_gcnte, NG);
    zero_buf(p_gcntn, NG);

    // stage 1: input projections + ssp
    gemm(node_feats, W_node1, p_n1, NN, HID);
    gemm(edge_feats, W_edge1, p_e1, NE, HID);
    gemm(glob_feats, W_glob1, p_g1, NG, HID);

    // EdgeModel: gather fused into GEMM A-loader
    gemm_edge(W_edge_mlp, p_emid, src, dst, batch);

    // scatter e -> nodes and graphs
    scatter_edges_kernel<<<NE, 256>>>(src, dst, batch);

    // NodeModel
    build_node_in_kernel<<<NN, 192>>>(batch);
    gemm(p_nin, W_node_mlp, p_nmid, NN, 3 * BHD);

    // scatter n -> graphs
    scatter_nodes_kernel<<<NN, 256>>>(batch);

    // GlobalModel
    build_glob_in_kernel<<<NG, 192>>>();
    gemm(p_gin, W_glob_mlp, p_gmid, NG, 3 * BHD);

    // output projections + ssp + residual
    gemm_add(p_nmid, W_node2, node_feats, out_n, NN, BHD);
    gemm_add(p_emid, W_edge2, edge_feats, out_e, NE, BHD);
    gemm_add(p_gmid, W_glob2, glob_feats, out_g, NG, BHD);
}